// round 1
// baseline (speedup 1.0000x reference)
#include <cuda_runtime.h>
#include <math.h>

#define NT 4096      // tokens = B*S
#define ND 1024      // hidden
#define NH 512       // intermediate
#define NE 8         // experts
#define NK 2         // top-k

#define BM 64
#define BN 64
#define BK 16

// ---- device scratch (static: no allocations allowed) ----
__device__ int   g_cnt[NE];
__device__ int   g_tokslot[NE * NT];                 // t*2 + k
__device__ float g_gate[NE * NT];
__device__ float g_h[(size_t)NE * NT * NH];          // 64 MB activated hidden
__device__ float g_y[(size_t)NT * NK * ND];          // 32 MB per-slot expert output
__device__ float g_logits_scratch[(size_t)NT * NE];  // fallback if out buf lacks logits

__global__ void init_kernel() {
    if (threadIdx.x < NE) g_cnt[threadIdx.x] = 0;
}

// One block per token: 8 warps -> 8 expert logits, then top-2 softmax dispatch.
__global__ void router_kernel(const float* __restrict__ x,
                              const float* __restrict__ wr,
                              float* __restrict__ logits_out) {
    int t = blockIdx.x;
    int w = threadIdx.x >> 5;
    int l = threadIdx.x & 31;
    const float* xr = x + (size_t)t * ND;
    const float* wrow = wr + w * ND;
    float s = 0.f;
    #pragma unroll 8
    for (int j = l; j < ND; j += 32) s += xr[j] * wrow[j];
    #pragma unroll
    for (int o = 16; o > 0; o >>= 1) s += __shfl_xor_sync(0xffffffffu, s, o);
    __shared__ float lg[NE];
    if (l == 0) { lg[w] = s; logits_out[(size_t)t * NE + w] = s; }
    __syncthreads();
    if (threadIdx.x == 0) {
        // top-2 (first-occurrence tie-break, matching lax.top_k)
        int i0 = 0; float v0 = lg[0];
        #pragma unroll
        for (int e = 1; e < NE; ++e) if (lg[e] > v0) { v0 = lg[e]; i0 = e; }
        int i1 = -1; float v1 = -INFINITY;
        #pragma unroll
        for (int e = 0; e < NE; ++e) if (e != i0 && lg[e] > v1) { v1 = lg[e]; i1 = e; }
        float e0 = expf(v0 - v0), e1 = expf(v1 - v0);
        float inv = 1.f / (e0 + e1);
        float gg0 = e0 * inv, gg1 = e1 * inv;
        int p0 = atomicAdd(&g_cnt[i0], 1);
        g_tokslot[i0 * NT + p0] = t * 2;
        g_gate[i0 * NT + p0]    = gg0;
        int p1 = atomicAdd(&g_cnt[i1], 1);
        g_tokslot[i1 * NT + p1] = t * 2 + 1;
        g_gate[i1 * NT + p1]    = gg1;
    }
}

// Grouped GEMM1 + fused SwiGLU.
// Block computes 64 gathered token rows x 64 cols of w_in: cols [n0,n0+32) from the
// "a" half (f in [0,H)) and [H+n0, H+n0+32) from the "b" half, then h = silu(a)*b.
__global__ void __launch_bounds__(256, 4)
ffn1_kernel(const float* __restrict__ x, const float* __restrict__ w_in) {
    int e = blockIdx.z;
    int cnt = g_cnt[e];
    int m0 = blockIdx.y * BM;
    if (m0 >= cnt) return;
    int n0 = blockIdx.x * 32;

    __shared__ float sm[64 * 64];       // reused: As[16][64]+Bs[16][64], then Cs[64][64]
    __shared__ int   stok[BM];
    float* As = sm;
    float* Bs = sm + BK * BM;

    int tid = threadIdx.x;
    if (tid < BM) {
        int r = m0 + tid;
        int rr = r < cnt ? r : cnt - 1;
        stok[tid] = g_tokslot[e * NT + rr] >> 1;
    }
    __syncthreads();

    int lm  = tid >> 2;          // 0..63 : row (A) / col (B) being loaded
    int lk4 = (tid & 3) * 4;     // k sub-offset 0,4,8,12

    int wn = (lm < 32) ? (n0 + lm) : (NH + n0 + (lm - 32));
    const float* wrow = w_in + ((size_t)e * (2 * NH) + wn) * ND;
    const float* xrow = x + (size_t)stok[lm] * ND;

    int ty = tid >> 4, tx = tid & 15;
    float acc[4][4];
    #pragma unroll
    for (int i = 0; i < 4; i++)
        #pragma unroll
        for (int j = 0; j < 4; j++) acc[i][j] = 0.f;

    for (int kb = 0; kb < ND; kb += BK) {
        float4 av = *reinterpret_cast<const float4*>(xrow + kb + lk4);
        float4 bv = *reinterpret_cast<const float4*>(wrow + kb + lk4);
        __syncthreads();
        As[(lk4 + 0) * BM + lm] = av.x;
        As[(lk4 + 1) * BM + lm] = av.y;
        As[(lk4 + 2) * BM + lm] = av.z;
        As[(lk4 + 3) * BM + lm] = av.w;
        Bs[(lk4 + 0) * BN + lm] = bv.x;
        Bs[(lk4 + 1) * BN + lm] = bv.y;
        Bs[(lk4 + 2) * BN + lm] = bv.z;
        Bs[(lk4 + 3) * BN + lm] = bv.w;
        __syncthreads();
        #pragma unroll
        for (int k = 0; k < BK; k++) {
            float4 a = *reinterpret_cast<float4*>(&As[k * BM + ty * 4]);
            float4 b = *reinterpret_cast<float4*>(&Bs[k * BN + tx * 4]);
            acc[0][0] += a.x * b.x; acc[0][1] += a.x * b.y; acc[0][2] += a.x * b.z; acc[0][3] += a.x * b.w;
            acc[1][0] += a.y * b.x; acc[1][1] += a.y * b.y; acc[1][2] += a.y * b.z; acc[1][3] += a.y * b.w;
            acc[2][0] += a.z * b.x; acc[2][1] += a.z * b.y; acc[2][2] += a.z * b.z; acc[2][3] += a.z * b.w;
            acc[3][0] += a.w * b.x; acc[3][1] += a.w * b.y; acc[3][2] += a.w * b.z; acc[3][3] += a.w * b.w;
        }
    }

    // park C in smem, pair a/b halves, apply SwiGLU, write h
    __syncthreads();
    float* Cs = sm;
    #pragma unroll
    for (int i = 0; i < 4; i++) {
        float4 v = make_float4(acc[i][0], acc[i][1], acc[i][2], acc[i][3]);
        *reinterpret_cast<float4*>(&Cs[(ty * 4 + i) * 64 + tx * 4]) = v;
    }
    __syncthreads();
    for (int idx = tid; idx < 64 * 32; idx += 256) {
        int m = idx >> 5, c = idx & 31;
        int r = m0 + m;
        if (r < cnt) {
            float a = Cs[m * 64 + c];
            float b = Cs[m * 64 + 32 + c];
            float hv = a / (1.f + expf(-a)) * b;   // silu(a)*b
            g_h[((size_t)e * NT + r) * NH + n0 + c] = hv;
        }
    }
}

// Grouped GEMM2: y = gate * (h @ w_out[e]^T), scattered to per-(token,slot) rows.
__global__ void __launch_bounds__(256, 4)
ffn2_kernel(const float* __restrict__ w_out) {
    int e = blockIdx.z;
    int cnt = g_cnt[e];
    int m0 = blockIdx.y * BM;
    if (m0 >= cnt) return;
    int n0 = blockIdx.x * BN;

    __shared__ float sm[2 * BK * 64];
    float* As = sm;
    float* Bs = sm + BK * BM;

    int tid = threadIdx.x;
    int lm  = tid >> 2;
    int lk4 = (tid & 3) * 4;

    int rr = (m0 + lm < cnt) ? (m0 + lm) : (cnt - 1);
    const float* arow = g_h  + ((size_t)e * NT + rr) * NH;
    const float* wrow = w_out + ((size_t)e * ND + n0 + lm) * NH;

    int ty = tid >> 4, tx = tid & 15;
    float acc[4][4];
    #pragma unroll
    for (int i = 0; i < 4; i++)
        #pragma unroll
        for (int j = 0; j < 4; j++) acc[i][j] = 0.f;

    for (int kb = 0; kb < NH; kb += BK) {
        float4 av = *reinterpret_cast<const float4*>(arow + kb + lk4);
        float4 bv = *reinterpret_cast<const float4*>(wrow + kb + lk4);
        __syncthreads();
        As[(lk4 + 0) * BM + lm] = av.x;
        As[(lk4 + 1) * BM + lm] = av.y;
        As[(lk4 + 2) * BM + lm] = av.z;
        As[(lk4 + 3) * BM + lm] = av.w;
        Bs[(lk4 + 0) * BN + lm] = bv.x;
        Bs[(lk4 + 1) * BN + lm] = bv.y;
        Bs[(lk4 + 2) * BN + lm] = bv.z;
        Bs[(lk4 + 3) * BN + lm] = bv.w;
        __syncthreads();
        #pragma unroll
        for (int k = 0; k < BK; k++) {
            float4 a = *reinterpret_cast<float4*>(&As[k * BM + ty * 4]);
            float4 b = *reinterpret_cast<float4*>(&Bs[k * BN + tx * 4]);
            acc[0][0] += a.x * b.x; acc[0][1] += a.x * b.y; acc[0][2] += a.x * b.z; acc[0][3] += a.x * b.w;
            acc[1][0] += a.y * b.x; acc[1][1] += a.y * b.y; acc[1][2] += a.y * b.z; acc[1][3] += a.y * b.w;
            acc[2][0] += a.z * b.x; acc[2][1] += a.z * b.y; acc[2][2] += a.z * b.z; acc[2][3] += a.z * b.w;
            acc[3][0] += a.w * b.x; acc[3][1] += a.w * b.y; acc[3][2] += a.w * b.z; acc[3][3] += a.w * b.w;
        }
    }

    #pragma unroll
    for (int i = 0; i < 4; i++) {
        int r = m0 + ty * 4 + i;
        if (r < cnt) {
            int   ts = g_tokslot[e * NT + r];
            float gt = g_gate[e * NT + r];
            float4 v = make_float4(acc[i][0] * gt, acc[i][1] * gt,
                                   acc[i][2] * gt, acc[i][3] * gt);
            *reinterpret_cast<float4*>(g_y + (size_t)ts * ND + n0 + tx * 4) = v;
        }
    }
}

// out[t] = y[2t] + y[2t+1]  (fixed order -> deterministic)
__global__ void combine_kernel(float* __restrict__ out) {
    int i = blockIdx.x * blockDim.x + threadIdx.x;       // over NT*ND/4 float4s
    if (i < NT * ND / 4) {
        int t = i >> 8, c = i & 255;
        const float4* y4 = reinterpret_cast<const float4*>(g_y);
        float4 a = y4[(size_t)(2 * t) * 256 + c];
        float4 b = y4[(size_t)(2 * t + 1) * 256 + c];
        reinterpret_cast<float4*>(out)[i] =
            make_float4(a.x + b.x, a.y + b.y, a.z + b.z, a.w + b.w);
    }
}

extern "C" void kernel_launch(void* const* d_in, const int* in_sizes, int n_in,
                              void* d_out, int out_size) {
    const float* x     = (const float*)d_in[0];
    const float* wr    = (const float*)d_in[1];
    const float* w_in  = (const float*)d_in[2];
    const float* w_out = (const float*)d_in[3];
    float* out = (float*)d_out;

    // router_logits are the second output; if the harness concatenated both
    // outputs they live at out + T*D, otherwise dump them to scratch.
    float* logits;
    if (out_size >= NT * ND + NT * NE) {
        logits = out + (size_t)NT * ND;
    } else {
        cudaGetSymbolAddress((void**)&logits, g_logits_scratch);
    }

    init_kernel<<<1, 32>>>();
    router_kernel<<<NT, 256>>>(x, wr, logits);
    ffn1_kernel<<<dim3(NH / 32, NT / BM, NE), 256>>>(x, w_in);
    ffn2_kernel<<<dim3(ND / BN, NT / BM, NE), 256>>>(w_out);
    combine_kernel<<<(NT * ND / 4 + 255) / 256, 256>>>(out);
}

// round 2
// speedup vs baseline: 3.1036x; 3.1036x over previous
#include <cuda_runtime.h>
#include <math.h>

#define NT 4096      // tokens = B*S
#define ND 1024      // hidden
#define NH 512       // intermediate
#define NE 8         // experts

// ---- device scratch (static: no allocations allowed) ----
__device__ int   g_cnt[NE];
__device__ int   g_tokslot[NE * NT];                 // t*2 + k
__device__ float g_gate[NE * NT];
__device__ float g_h[(size_t)NE * NT * NH];          // activated hidden (compacted per expert)
__device__ float g_y[(size_t)NT * 2 * ND];           // per-(token,slot) expert output
__device__ float g_logits_scratch[(size_t)NT * NE];

__global__ void init_kernel() {
    if (threadIdx.x < NE) g_cnt[threadIdx.x] = 0;
}

// One block per token: 8 warps -> 8 expert logits, then top-2 softmax dispatch.
__global__ void router_kernel(const float* __restrict__ x,
                              const float* __restrict__ wr,
                              float* __restrict__ logits_out) {
    int t = blockIdx.x;
    int w = threadIdx.x >> 5;
    int l = threadIdx.x & 31;
    const float* xr = x + (size_t)t * ND;
    const float* wrow = wr + w * ND;
    float s = 0.f;
    #pragma unroll 8
    for (int j = l; j < ND; j += 32) s += xr[j] * wrow[j];
    #pragma unroll
    for (int o = 16; o > 0; o >>= 1) s += __shfl_xor_sync(0xffffffffu, s, o);
    __shared__ float lg[NE];
    if (l == 0) { lg[w] = s; logits_out[(size_t)t * NE + w] = s; }
    __syncthreads();
    if (threadIdx.x == 0) {
        int i0 = 0; float v0 = lg[0];
        #pragma unroll
        for (int e = 1; e < NE; ++e) if (lg[e] > v0) { v0 = lg[e]; i0 = e; }
        int i1 = -1; float v1 = -INFINITY;
        #pragma unroll
        for (int e = 0; e < NE; ++e) if (e != i0 && lg[e] > v1) { v1 = lg[e]; i1 = e; }
        float e1 = expf(v1 - v0);
        float inv = 1.f / (1.f + e1);
        float gg0 = inv, gg1 = e1 * inv;
        int p0 = atomicAdd(&g_cnt[i0], 1);
        g_tokslot[i0 * NT + p0] = t * 2;
        g_gate[i0 * NT + p0]    = gg0;
        int p1 = atomicAdd(&g_cnt[i1], 1);
        g_tokslot[i1 * NT + p1] = t * 2 + 1;
        g_gate[i1 * NT + p1]    = gg1;
    }
}

// ---- TF32 tensor-core helpers ----
__device__ __forceinline__ unsigned f2tf(float f) {
    unsigned u;
    asm("cvt.rna.tf32.f32 %0, %1;" : "=r"(u) : "f"(f));
    return u;
}

__device__ __forceinline__ void mma8(float* d, const unsigned* a, const unsigned* b) {
    asm volatile(
        "mma.sync.aligned.m16n8k8.row.col.f32.tf32.tf32.f32 "
        "{%0,%1,%2,%3}, {%4,%5,%6,%7}, {%8,%9}, {%0,%1,%2,%3};"
        : "+f"(d[0]), "+f"(d[1]), "+f"(d[2]), "+f"(d[3])
        : "r"(a[0]), "r"(a[1]), "r"(a[2]), "r"(a[3]), "r"(b[0]), "r"(b[1]));
}

// XOR swizzle: conflict-free fragment loads for [row][32] fp32 tiles
#define SW(m, k) ((k) ^ (((m) & 7) << 2))

// =====================================================================
// ffn1: grouped TF32 GEMM (gathered token rows x w_in cols) + SwiGLU.
// Block tile: 128 rows x 64 cols (32 a-cols paired with 32 b-cols), BK=32.
// 128 threads = 4 warps, warp tile 64x32.
// =====================================================================
__global__ void __launch_bounds__(128)
ffn1_tc(const float* __restrict__ x, const float* __restrict__ w_in) {
    int e = blockIdx.z;
    int cnt = g_cnt[e];
    int m0 = blockIdx.y * 128;
    if (m0 >= cnt) return;
    int n0 = blockIdx.x * 32;

    __shared__ unsigned smem[12288];   // 2 stages x (A 128x32 | B 64x32); aliased as Cs later

    unsigned tid = threadIdx.x;
    unsigned lane = tid & 31, wid = tid >> 5;
    unsigned wm = wid >> 1, wn = wid & 1;
    unsigned grp = lane >> 2, tig = lane & 3;

    // global pointers (gathered A rows; B rows from a-half then b-half of w_in)
    const float* aptr[8];
    #pragma unroll
    for (int p = 0; p < 8; ++p) {
        int m = p * 16 + (tid >> 3);
        int r = m0 + m; if (r >= cnt) r = cnt - 1;
        int tok = g_tokslot[e * NT + r] >> 1;
        aptr[p] = x + (size_t)tok * ND + (tid & 7) * 4;
    }
    const float* bptr[4];
    #pragma unroll
    for (int p = 0; p < 4; ++p) {
        int n = p * 16 + (tid >> 3);
        int wr = (n < 32) ? (n0 + n) : (NH + n0 + n - 32);
        bptr[p] = w_in + ((size_t)e * (2 * NH) + wr) * ND + (tid & 7) * 4;
    }

    float acc[4][4][4];
    #pragma unroll
    for (int i = 0; i < 4; ++i)
        #pragma unroll
        for (int j = 0; j < 4; ++j)
            #pragma unroll
            for (int q = 0; q < 4; ++q) acc[i][j][q] = 0.f;

    float4 ra[8], rb[4];
    #pragma unroll
    for (int p = 0; p < 8; ++p) { ra[p] = *(const float4*)aptr[p]; aptr[p] += 32; }
    #pragma unroll
    for (int p = 0; p < 4; ++p) { rb[p] = *(const float4*)bptr[p]; bptr[p] += 32; }

    unsigned buf = 0;
    const int NITER = ND / 32;
    for (int it = 0; it < NITER; ++it) {
        unsigned* As = smem + buf * 6144;
        unsigned* Bs = As + 4096;
        unsigned k4 = (tid & 7) * 4;
        #pragma unroll
        for (int p = 0; p < 8; ++p) {
            unsigned m = p * 16 + (tid >> 3);
            unsigned off = m * 32 + SW(m, k4);
            As[off + 0] = f2tf(ra[p].x); As[off + 1] = f2tf(ra[p].y);
            As[off + 2] = f2tf(ra[p].z); As[off + 3] = f2tf(ra[p].w);
        }
        #pragma unroll
        for (int p = 0; p < 4; ++p) {
            unsigned n = p * 16 + (tid >> 3);
            unsigned off = n * 32 + SW(n, k4);
            Bs[off + 0] = f2tf(rb[p].x); Bs[off + 1] = f2tf(rb[p].y);
            Bs[off + 2] = f2tf(rb[p].z); Bs[off + 3] = f2tf(rb[p].w);
        }
        __syncthreads();
        if (it + 1 < NITER) {
            #pragma unroll
            for (int p = 0; p < 8; ++p) { ra[p] = *(const float4*)aptr[p]; aptr[p] += 32; }
            #pragma unroll
            for (int p = 0; p < 4; ++p) { rb[p] = *(const float4*)bptr[p]; bptr[p] += 32; }
        }
        #pragma unroll
        for (int ks = 0; ks < 4; ++ks) {
            unsigned afr[4][4], bfr[4][2];
            unsigned k = ks * 8 + tig;
            #pragma unroll
            for (int mt = 0; mt < 4; ++mt) {
                unsigned m = wm * 64 + mt * 16 + grp;
                afr[mt][0] = As[m * 32 + SW(m, k)];
                afr[mt][1] = As[(m + 8) * 32 + SW(m + 8, k)];
                afr[mt][2] = As[m * 32 + SW(m, k + 4)];
                afr[mt][3] = As[(m + 8) * 32 + SW(m + 8, k + 4)];
            }
            #pragma unroll
            for (int nt = 0; nt < 4; ++nt) {
                unsigned n = wn * 32 + nt * 8 + grp;
                bfr[nt][0] = Bs[n * 32 + SW(n, k)];
                bfr[nt][1] = Bs[n * 32 + SW(n, k + 4)];
            }
            #pragma unroll
            for (int mt = 0; mt < 4; ++mt)
                #pragma unroll
                for (int nt = 0; nt < 4; ++nt)
                    mma8(acc[mt][nt], afr[mt], bfr[nt]);
        }
        buf ^= 1;
    }
    __syncthreads();

    // epilogue: park C in smem (aliased), pair a/b halves, SwiGLU, write h
    float* Cs = (float*)smem;   // [128][68]
    #pragma unroll
    for (int mt = 0; mt < 4; ++mt) {
        unsigned rr = wm * 64 + mt * 16 + grp;
        #pragma unroll
        for (int nt = 0; nt < 4; ++nt) {
            unsigned col = wn * 32 + nt * 8 + 2 * tig;
            Cs[rr * 68 + col]           = acc[mt][nt][0];
            Cs[rr * 68 + col + 1]       = acc[mt][nt][1];
            Cs[(rr + 8) * 68 + col]     = acc[mt][nt][2];
            Cs[(rr + 8) * 68 + col + 1] = acc[mt][nt][3];
        }
    }
    __syncthreads();
    for (int idx = tid; idx < 128 * 32; idx += 128) {
        int m = idx >> 5, c = idx & 31;
        int r = m0 + m;
        if (r < cnt) {
            float a = Cs[m * 68 + c];
            float b = Cs[m * 68 + 32 + c];
            g_h[((size_t)e * NT + r) * NH + n0 + c] = a / (1.f + expf(-a)) * b;
        }
    }
}

// =====================================================================
// ffn2: grouped TF32 GEMM (g_h rows x w_out rows), gate-scale + scatter.
// Block tile: 128 x 64, BK=32, K=512.
// =====================================================================
__global__ void __launch_bounds__(128)
ffn2_tc(const float* __restrict__ w_out) {
    int e = blockIdx.z;
    int cnt = g_cnt[e];
    int m0 = blockIdx.y * 128;
    if (m0 >= cnt) return;
    int n0 = blockIdx.x * 64;

    __shared__ unsigned smem[12288];

    unsigned tid = threadIdx.x;
    unsigned lane = tid & 31, wid = tid >> 5;
    unsigned wm = wid >> 1, wn = wid & 1;
    unsigned grp = lane >> 2, tig = lane & 3;

    const float* aptr[8];
    #pragma unroll
    for (int p = 0; p < 8; ++p) {
        int m = p * 16 + (tid >> 3);
        int r = m0 + m; if (r >= cnt) r = cnt - 1;
        aptr[p] = g_h + ((size_t)e * NT + r) * NH + (tid & 7) * 4;
    }
    const float* bptr[4];
    #pragma unroll
    for (int p = 0; p < 4; ++p) {
        int n = p * 16 + (tid >> 3);
        bptr[p] = w_out + ((size_t)e * ND + n0 + n) * NH + (tid & 7) * 4;
    }

    float acc[4][4][4];
    #pragma unroll
    for (int i = 0; i < 4; ++i)
        #pragma unroll
        for (int j = 0; j < 4; ++j)
            #pragma unroll
            for (int q = 0; q < 4; ++q) acc[i][j][q] = 0.f;

    float4 ra[8], rb[4];
    #pragma unroll
    for (int p = 0; p < 8; ++p) { ra[p] = *(const float4*)aptr[p]; aptr[p] += 32; }
    #pragma unroll
    for (int p = 0; p < 4; ++p) { rb[p] = *(const float4*)bptr[p]; bptr[p] += 32; }

    unsigned buf = 0;
    const int NITER = NH / 32;
    for (int it = 0; it < NITER; ++it) {
        unsigned* As = smem + buf * 6144;
        unsigned* Bs = As + 4096;
        unsigned k4 = (tid & 7) * 4;
        #pragma unroll
        for (int p = 0; p < 8; ++p) {
            unsigned m = p * 16 + (tid >> 3);
            unsigned off = m * 32 + SW(m, k4);
            As[off + 0] = f2tf(ra[p].x); As[off + 1] = f2tf(ra[p].y);
            As[off + 2] = f2tf(ra[p].z); As[off + 3] = f2tf(ra[p].w);
        }
        #pragma unroll
        for (int p = 0; p < 4; ++p) {
            unsigned n = p * 16 + (tid >> 3);
            unsigned off = n * 32 + SW(n, k4);
            Bs[off + 0] = f2tf(rb[p].x); Bs[off + 1] = f2tf(rb[p].y);
            Bs[off + 2] = f2tf(rb[p].z); Bs[off + 3] = f2tf(rb[p].w);
        }
        __syncthreads();
        if (it + 1 < NITER) {
            #pragma unroll
            for (int p = 0; p < 8; ++p) { ra[p] = *(const float4*)aptr[p]; aptr[p] += 32; }
            #pragma unroll
            for (int p = 0; p < 4; ++p) { rb[p] = *(const float4*)bptr[p]; bptr[p] += 32; }
        }
        #pragma unroll
        for (int ks = 0; ks < 4; ++ks) {
            unsigned afr[4][4], bfr[4][2];
            unsigned k = ks * 8 + tig;
            #pragma unroll
            for (int mt = 0; mt < 4; ++mt) {
                unsigned m = wm * 64 + mt * 16 + grp;
                afr[mt][0] = As[m * 32 + SW(m, k)];
                afr[mt][1] = As[(m + 8) * 32 + SW(m + 8, k)];
                afr[mt][2] = As[m * 32 + SW(m, k + 4)];
                afr[mt][3] = As[(m + 8) * 32 + SW(m + 8, k + 4)];
            }
            #pragma unroll
            for (int nt = 0; nt < 4; ++nt) {
                unsigned n = wn * 32 + nt * 8 + grp;
                bfr[nt][0] = Bs[n * 32 + SW(n, k)];
                bfr[nt][1] = Bs[n * 32 + SW(n, k + 4)];
            }
            #pragma unroll
            for (int mt = 0; mt < 4; ++mt)
                #pragma unroll
                for (int nt = 0; nt < 4; ++nt)
                    mma8(acc[mt][nt], afr[mt], bfr[nt]);
        }
        buf ^= 1;
    }

    // epilogue: gate-scale, scatter per (token,slot) row
    #pragma unroll
    for (int mt = 0; mt < 4; ++mt) {
        int r0 = m0 + wm * 64 + mt * 16 + grp;
        int r1 = r0 + 8;
        int ts0 = 0, ts1 = 0; float gt0 = 0.f, gt1 = 0.f;
        if (r0 < cnt) { ts0 = g_tokslot[e * NT + r0]; gt0 = g_gate[e * NT + r0]; }
        if (r1 < cnt) { ts1 = g_tokslot[e * NT + r1]; gt1 = g_gate[e * NT + r1]; }
        #pragma unroll
        for (int nt = 0; nt < 4; ++nt) {
            int col = n0 + wn * 32 + nt * 8 + 2 * tig;
            if (r0 < cnt) {
                float2 v = make_float2(acc[mt][nt][0] * gt0, acc[mt][nt][1] * gt0);
                *(float2*)(g_y + (size_t)ts0 * ND + col) = v;
            }
            if (r1 < cnt) {
                float2 v = make_float2(acc[mt][nt][2] * gt1, acc[mt][nt][3] * gt1);
                *(float2*)(g_y + (size_t)ts1 * ND + col) = v;
            }
        }
    }
}

// out[t] = y[2t] + y[2t+1]  (fixed order -> deterministic)
__global__ void combine_kernel(float* __restrict__ out) {
    int i = blockIdx.x * blockDim.x + threadIdx.x;
    if (i < NT * ND / 4) {
        int t = i >> 8, c = i & 255;
        const float4* y4 = reinterpret_cast<const float4*>(g_y);
        float4 a = y4[(size_t)(2 * t) * 256 + c];
        float4 b = y4[(size_t)(2 * t + 1) * 256 + c];
        reinterpret_cast<float4*>(out)[i] =
            make_float4(a.x + b.x, a.y + b.y, a.z + b.z, a.w + b.w);
    }
}

extern "C" void kernel_launch(void* const* d_in, const int* in_sizes, int n_in,
                              void* d_out, int out_size) {
    const float* x     = (const float*)d_in[0];
    const float* wr    = (const float*)d_in[1];
    const float* w_in  = (const float*)d_in[2];
    const float* w_out = (const float*)d_in[3];
    float* out = (float*)d_out;

    float* logits;
    if (out_size >= NT * ND + NT * NE) {
        logits = out + (size_t)NT * ND;
    } else {
        cudaGetSymbolAddress((void**)&logits, g_logits_scratch);
    }

    init_kernel<<<1, 32>>>();
    router_kernel<<<NT, 256>>>(x, wr, logits);
    ffn1_tc<<<dim3(NH / 32, NT / 128, NE), 128>>>(x, w_in);
    ffn2_tc<<<dim3(ND / 64, NT / 128, NE), 128>>>(w_out);
    combine_kernel<<<(NT * ND / 4 + 255) / 256, 256>>>(out);
}

// round 4
// speedup vs baseline: 5.5244x; 1.7800x over previous
#include <cuda_runtime.h>
#include <cuda_fp16.h>
#include <math.h>
#include <stdint.h>

#define NT 4096      // tokens = B*S
#define ND 1024      // hidden
#define NH 512       // intermediate
#define NE 8         // experts

// ---- device scratch (static; no allocations allowed) ----
__device__ int    g_cnt[NE];
__device__ int    g_tokslot[NE * NT];
__device__ float  g_gate[NE * NT];
__device__ __half g_x16[(size_t)NT * ND];
__device__ __half g_win16[(size_t)NE * 2 * NH * ND];
__device__ __half g_wout16[(size_t)NE * ND * NH];
__device__ __half g_h16[(size_t)NE * NT * NH];
__device__ float  g_y[(size_t)NT * 2 * ND];
__device__ float  g_logits_scratch[(size_t)NT * NE];

// ======================= helpers =======================
__device__ __forceinline__ uint32_t smem_u32(const void* p) {
    uint32_t a;
    asm("{ .reg .u64 t; cvta.to.shared.u64 t, %1; cvt.u32.u64 %0, t; }" : "=r"(a) : "l"(p));
    return a;
}
#define CPA16(dst, src) asm volatile("cp.async.cg.shared.global [%0], [%1], 16;" :: "r"(dst), "l"(src))
#define CPCOMMIT()      asm volatile("cp.async.commit_group;")
#define CPWAIT(n)       asm volatile("cp.async.wait_group %0;" :: "n"(n))
#define LDM_X4(r0, r1, r2, r3, addr) \
    asm volatile("ldmatrix.sync.aligned.m8n8.x4.shared.b16 {%0,%1,%2,%3}, [%4];" \
        : "=r"(r0), "=r"(r1), "=r"(r2), "=r"(r3) : "r"(addr))
#define MMA16(d, a, b0, b1) \
    asm volatile("mma.sync.aligned.m16n8k16.row.col.f32.f16.f16.f32 " \
        "{%0,%1,%2,%3}, {%4,%5,%6,%7}, {%8,%9}, {%0,%1,%2,%3};" \
        : "+f"((d)[0]), "+f"((d)[1]), "+f"((d)[2]), "+f"((d)[3]) \
        : "r"((a)[0]), "r"((a)[1]), "r"((a)[2]), "r"((a)[3]), "r"(b0), "r"(b1))

// =====================================================================
__global__ void init_kernel() {
    if (threadIdx.x < NE) g_cnt[threadIdx.x] = 0;
}

__global__ void router_kernel(const float* __restrict__ x,
                              const float* __restrict__ wr,
                              float* __restrict__ logits_out) {
    int t = blockIdx.x;
    int w = threadIdx.x >> 5;
    int l = threadIdx.x & 31;
    const float* xr = x + (size_t)t * ND;
    const float* wrow = wr + w * ND;
    float s = 0.f;
    #pragma unroll 8
    for (int j = l; j < ND; j += 32) s += xr[j] * wrow[j];
    #pragma unroll
    for (int o = 16; o > 0; o >>= 1) s += __shfl_xor_sync(0xffffffffu, s, o);
    __shared__ float lg[NE];
    if (l == 0) { lg[w] = s; logits_out[(size_t)t * NE + w] = s; }
    __syncthreads();
    if (threadIdx.x == 0) {
        int i0 = 0; float v0 = lg[0];
        #pragma unroll
        for (int e = 1; e < NE; ++e) if (lg[e] > v0) { v0 = lg[e]; i0 = e; }
        int i1 = -1; float v1 = -INFINITY;
        #pragma unroll
        for (int e = 0; e < NE; ++e) if (e != i0 && lg[e] > v1) { v1 = lg[e]; i1 = e; }
        float e1 = expf(v1 - v0);
        float inv = 1.f / (1.f + e1);
        int p0 = atomicAdd(&g_cnt[i0], 1);
        g_tokslot[i0 * NT + p0] = t * 2;
        g_gate[i0 * NT + p0]    = inv;
        int p1 = atomicAdd(&g_cnt[i1], 1);
        g_tokslot[i1 * NT + p1] = t * 2 + 1;
        g_gate[i1 * NT + p1]    = e1 * inv;
    }
}

// fp32 -> fp16 bulk convert (vectorized)
__global__ void cvt_kernel(const float* __restrict__ s, __half* __restrict__ d, int n4) {
    int i = blockIdx.x * blockDim.x + threadIdx.x;
    if (i < n4) {
        float4 v = reinterpret_cast<const float4*>(s)[i];
        __half2 h0 = __floats2half2_rn(v.x, v.y);
        __half2 h1 = __floats2half2_rn(v.z, v.w);
        reinterpret_cast<__half2*>(d)[2 * i]     = h0;
        reinterpret_cast<__half2*>(d)[2 * i + 1] = h1;
    }
}

// Shared-mem geometry: row = 64B (32 halfs), chunk = 16B, swizzle c^=((row>>1)&3).
// Stage = A(128x32h, 8KB) + B(128x32h, 8KB) = 16KB; 3 stages = 48KB.
#define STAGE_BYTES 16384

// =====================================================================
// ffn1: C[128 x 128] = A(gathered x16 rows) @ B(w_in16: 64 a-rows | 64 b-rows)^T,
// fp16 mma, K = 1024. Epilogue: h = silu(a)*b -> g_h16 (64 h-cols per block).
// =====================================================================
__global__ void __launch_bounds__(256, 2)
ffn1_h(void) {
    __shared__ __align__(128) uint8_t smem[3 * STAGE_BYTES];
    int e = blockIdx.z;
    int cnt = g_cnt[e];
    int m0 = blockIdx.y * 128;
    if (m0 >= cnt) return;
    int n0 = blockIdx.x * 64;

    uint32_t sb = smem_u32(smem);
    int t = threadIdx.x;
    int lane = t & 31, wid = t >> 5;
    int wm = wid & 1, wn = wid >> 1;          // warp grid 2(M) x 4(N)
    int grp = lane >> 2, tig = lane & 3;
    int rA = (lane & 7) + ((lane >> 3) & 1) * 8;   // ldmatrix row-in-16
    int csel = lane >> 4;                          // ldmatrix chunk select

    // loader: each thread owns chunk (row lr & lr+64, chunk lc) of A and B
    int lr = t >> 2;             // 0..63
    int lc = t & 3;
    int r0 = m0 + lr, r1 = r0 + 64;
    int rc0 = r0 < cnt ? r0 : cnt - 1;
    int rc1 = r1 < cnt ? r1 : cnt - 1;
    const __half* asrc0 = g_x16 + (size_t)(g_tokslot[e * NT + rc0] >> 1) * ND + lc * 8;
    const __half* asrc1 = g_x16 + (size_t)(g_tokslot[e * NT + rc1] >> 1) * ND + lc * 8;
    const __half* bsrc0 = g_win16 + ((size_t)e * (2 * NH) + n0 + lr) * ND + lc * 8;
    const __half* bsrc1 = g_win16 + ((size_t)e * (2 * NH) + NH + n0 + lr) * ND + lc * 8;
    uint32_t swc = (uint32_t)((lc ^ ((lr >> 1) & 3)) << 4);
    uint32_t dA0 = lr * 64 + swc;
    uint32_t dA1 = dA0 + 4096;

    float acc[4][4][4];
    #pragma unroll
    for (int i = 0; i < 4; ++i)
        #pragma unroll
        for (int j = 0; j < 4; ++j)
            #pragma unroll
            for (int q = 0; q < 4; ++q) acc[i][j][q] = 0.f;

    #pragma unroll
    for (int s = 0; s < 2; ++s) {
        uint32_t st = sb + s * STAGE_BYTES;
        CPA16(st + dA0, asrc0 + s * 32);
        CPA16(st + dA1, asrc1 + s * 32);
        CPA16(st + 8192 + dA0, bsrc0 + s * 32);
        CPA16(st + 8192 + dA1, bsrc1 + s * 32);
        CPCOMMIT();
    }

    const int NK = ND / 32;   // 32
    int stage = 0;
    for (int kt = 0; kt < NK; ++kt) {
        if (kt < NK - 1) { CPWAIT(1); } else { CPWAIT(0); }
        __syncthreads();
        if (kt + 2 < NK) {
            uint32_t st = sb + ((kt + 2) % 3) * STAGE_BYTES;
            int off = (kt + 2) * 32;
            CPA16(st + dA0, asrc0 + off);
            CPA16(st + dA1, asrc1 + off);
            CPA16(st + 8192 + dA0, bsrc0 + off);
            CPA16(st + 8192 + dA1, bsrc1 + off);
            CPCOMMIT();
        }
        uint32_t As = sb + stage * STAGE_BYTES;
        uint32_t Bs = As + 8192;
        #pragma unroll
        for (int ks = 0; ks < 2; ++ks) {
            uint32_t a[4][4], B0[4], B1[4];
            int ch = ks * 2 + csel;
            #pragma unroll
            for (int mt = 0; mt < 4; ++mt) {
                int row = wm * 64 + mt * 16 + rA;
                uint32_t ad = As + row * 64 + ((ch ^ ((row >> 1) & 3)) << 4);
                LDM_X4(a[mt][0], a[mt][1], a[mt][2], a[mt][3], ad);
            }
            {
                int row = wn * 32 + rA;
                uint32_t bd = Bs + row * 64 + ((ch ^ ((row >> 1) & 3)) << 4);
                LDM_X4(B0[0], B0[1], B0[2], B0[3], bd);
                row += 16;
                bd = Bs + row * 64 + ((ch ^ ((row >> 1) & 3)) << 4);
                LDM_X4(B1[0], B1[1], B1[2], B1[3], bd);
            }
            #pragma unroll
            for (int mt = 0; mt < 4; ++mt) {
                MMA16(acc[mt][0], a[mt], B0[0], B0[2]);
                MMA16(acc[mt][1], a[mt], B0[1], B0[3]);
                MMA16(acc[mt][2], a[mt], B1[0], B1[2]);
                MMA16(acc[mt][3], a[mt], B1[1], B1[3]);
            }
        }
        stage = stage + 1; if (stage == 3) stage = 0;
    }

    // epilogue: b-half (cols 64..128 -> warps wn>=2) staged in smem, a-warps fuse SwiGLU
    __syncthreads();
    float* Cb = (float*)smem;   // [128][66]
    if (wn >= 2) {
        #pragma unroll
        for (int mt = 0; mt < 4; ++mt) {
            int row = wm * 64 + mt * 16 + grp;
            #pragma unroll
            for (int nt = 0; nt < 4; ++nt) {
                int col = (wn - 2) * 32 + nt * 8 + 2 * tig;
                Cb[row * 66 + col]           = acc[mt][nt][0];
                Cb[row * 66 + col + 1]       = acc[mt][nt][1];
                Cb[(row + 8) * 66 + col]     = acc[mt][nt][2];
                Cb[(row + 8) * 66 + col + 1] = acc[mt][nt][3];
            }
        }
    }
    __syncthreads();
    if (wn < 2) {
        #pragma unroll
        for (int mt = 0; mt < 4; ++mt) {
            #pragma unroll
            for (int hf = 0; hf < 2; ++hf) {
                int row = wm * 64 + mt * 16 + grp + hf * 8;
                int r = m0 + row;
                if (r < cnt) {
                    __half* dst = g_h16 + ((size_t)e * NT + r) * NH + n0;
                    #pragma unroll
                    for (int nt = 0; nt < 4; ++nt) {
                        int col = wn * 32 + nt * 8 + 2 * tig;
                        float a0 = acc[mt][nt][hf * 2 + 0];
                        float a1 = acc[mt][nt][hf * 2 + 1];
                        float b0 = Cb[row * 66 + col];
                        float b1 = Cb[row * 66 + col + 1];
                        float h0 = a0 / (1.f + expf(-a0)) * b0;
                        float h1 = a1 / (1.f + expf(-a1)) * b1;
                        *(__half2*)(dst + col) = __floats2half2_rn(h0, h1);
                    }
                }
            }
        }
    }
}

// =====================================================================
// ffn2: C[128 x 128] = g_h16 rows @ w_out16 rows^T, K = 512.
// Epilogue: gate-scale, scatter rows to g_y[tokslot].
// =====================================================================
__global__ void __launch_bounds__(256, 2)
ffn2_h(void) {
    __shared__ __align__(128) uint8_t smem[3 * STAGE_BYTES];
    int e = blockIdx.z;
    int cnt = g_cnt[e];
    int m0 = blockIdx.y * 128;
    if (m0 >= cnt) return;
    int n0 = blockIdx.x * 128;

    uint32_t sb = smem_u32(smem);
    int t = threadIdx.x;
    int lane = t & 31, wid = t >> 5;
    int wm = wid & 1, wn = wid >> 1;
    int grp = lane >> 2, tig = lane & 3;
    int rA = (lane & 7) + ((lane >> 3) & 1) * 8;
    int csel = lane >> 4;

    int lr = t >> 2;
    int lc = t & 3;
    int r0 = m0 + lr, r1 = r0 + 64;
    int rc0 = r0 < cnt ? r0 : cnt - 1;
    int rc1 = r1 < cnt ? r1 : cnt - 1;
    const __half* asrc0 = g_h16 + ((size_t)e * NT + rc0) * NH + lc * 8;
    const __half* asrc1 = g_h16 + ((size_t)e * NT + rc1) * NH + lc * 8;
    const __half* bsrc0 = g_wout16 + ((size_t)e * ND + n0 + lr) * NH + lc * 8;
    const __half* bsrc1 = g_wout16 + ((size_t)e * ND + n0 + lr + 64) * NH + lc * 8;
    uint32_t swc = (uint32_t)((lc ^ ((lr >> 1) & 3)) << 4);
    uint32_t dA0 = lr * 64 + swc;
    uint32_t dA1 = dA0 + 4096;

    float acc[4][4][4];
    #pragma unroll
    for (int i = 0; i < 4; ++i)
        #pragma unroll
        for (int j = 0; j < 4; ++j)
            #pragma unroll
            for (int q = 0; q < 4; ++q) acc[i][j][q] = 0.f;

    #pragma unroll
    for (int s = 0; s < 2; ++s) {
        uint32_t st = sb + s * STAGE_BYTES;
        CPA16(st + dA0, asrc0 + s * 32);
        CPA16(st + dA1, asrc1 + s * 32);
        CPA16(st + 8192 + dA0, bsrc0 + s * 32);
        CPA16(st + 8192 + dA1, bsrc1 + s * 32);
        CPCOMMIT();
    }

    const int NK = NH / 32;   // 16
    int stage = 0;
    for (int kt = 0; kt < NK; ++kt) {
        if (kt < NK - 1) { CPWAIT(1); } else { CPWAIT(0); }
        __syncthreads();
        if (kt + 2 < NK) {
            uint32_t st = sb + ((kt + 2) % 3) * STAGE_BYTES;
            int off = (kt + 2) * 32;
            CPA16(st + dA0, asrc0 + off);
            CPA16(st + dA1, asrc1 + off);
            CPA16(st + 8192 + dA0, bsrc0 + off);
            CPA16(st + 8192 + dA1, bsrc1 + off);
            CPCOMMIT();
        }
        uint32_t As = sb + stage * STAGE_BYTES;
        uint32_t Bs = As + 8192;
        #pragma unroll
        for (int ks = 0; ks < 2; ++ks) {
            uint32_t a[4][4], B0[4], B1[4];
            int ch = ks * 2 + csel;
            #pragma unroll
            for (int mt = 0; mt < 4; ++mt) {
                int row = wm * 64 + mt * 16 + rA;
                uint32_t ad = As + row * 64 + ((ch ^ ((row >> 1) & 3)) << 4);
                LDM_X4(a[mt][0], a[mt][1], a[mt][2], a[mt][3], ad);
            }
            {
                int row = wn * 32 + rA;
                uint32_t bd = Bs + row * 64 + ((ch ^ ((row >> 1) & 3)) << 4);
                LDM_X4(B0[0], B0[1], B0[2], B0[3], bd);
                row += 16;
                bd = Bs + row * 64 + ((ch ^ ((row >> 1) & 3)) << 4);
                LDM_X4(B1[0], B1[1], B1[2], B1[3], bd);
            }
            #pragma unroll
            for (int mt = 0; mt < 4; ++mt) {
                MMA16(acc[mt][0], a[mt], B0[0], B0[2]);
                MMA16(acc[mt][1], a[mt], B0[1], B0[3]);
                MMA16(acc[mt][2], a[mt], B1[0], B1[2]);
                MMA16(acc[mt][3], a[mt], B1[1], B1[3]);
            }
        }
        stage = stage + 1; if (stage == 3) stage = 0;
    }

    #pragma unroll
    for (int mt = 0; mt < 4; ++mt) {
        #pragma unroll
        for (int hf = 0; hf < 2; ++hf) {
            int row = wm * 64 + mt * 16 + grp + hf * 8;
            int r = m0 + row;
            if (r < cnt) {
                int   ts = g_tokslot[e * NT + r];
                float gt = g_gate[e * NT + r];
                float* dst = g_y + (size_t)ts * ND + n0;
                #pragma unroll
                for (int nt = 0; nt < 4; ++nt) {
                    int col = wn * 32 + nt * 8 + 2 * tig;
                    float2 v = make_float2(acc[mt][nt][hf * 2 + 0] * gt,
                                           acc[mt][nt][hf * 2 + 1] * gt);
                    *(float2*)(dst + col) = v;
                }
            }
        }
    }
}

// out[t] = y[2t] + y[2t+1]
__global__ void combine_kernel(float* __restrict__ out) {
    int i = blockIdx.x * blockDim.x + threadIdx.x;
    if (i < NT * ND / 4) {
        int t = i >> 8, c = i & 255;
        const float4* y4 = reinterpret_cast<const float4*>(g_y);
        float4 a = y4[(size_t)(2 * t) * 256 + c];
        float4 b = y4[(size_t)(2 * t + 1) * 256 + c];
        reinterpret_cast<float4*>(out)[i] =
            make_float4(a.x + b.x, a.y + b.y, a.z + b.z, a.w + b.w);
    }
}

extern "C" void kernel_launch(void* const* d_in, const int* in_sizes, int n_in,
                              void* d_out, int out_size) {
    const float* x     = (const float*)d_in[0];
    const float* wr    = (const float*)d_in[1];
    const float* w_in  = (const float*)d_in[2];
    const float* w_out = (const float*)d_in[3];
    float* out = (float*)d_out;

    float* logits;
    if (out_size >= NT * ND + NT * NE) {
        logits = out + (size_t)NT * ND;
    } else {
        cudaGetSymbolAddress((void**)&logits, g_logits_scratch);
    }

    __half *px16, *pwin16, *pwout16;
    cudaGetSymbolAddress((void**)&px16, g_x16);
    cudaGetSymbolAddress((void**)&pwin16, g_win16);
    cudaGetSymbolAddress((void**)&pwout16, g_wout16);

    init_kernel<<<1, 32>>>();
    router_kernel<<<NT, 256>>>(x, wr, logits);

    const int nx = NT * ND / 4, nwi = NE * 2 * NH * ND / 4, nwo = NE * ND * NH / 4;
    cvt_kernel<<<(nx  + 255) / 256, 256>>>(x,     px16,   nx);
    cvt_kernel<<<(nwi + 255) / 256, 256>>>(w_in,  pwin16, nwi);
    cvt_kernel<<<(nwo + 255) / 256, 256>>>(w_out, pwout16, nwo);

    ffn1_h<<<dim3(NH / 64, NT / 128, NE), 256>>>();
    ffn2_h<<<dim3(ND / 128, NT / 128, NE), 256>>>();
    combine_kernel<<<(NT * ND / 4 + 255) / 256, 256>>>(out);
}